// round 14
// baseline (speedup 1.0000x reference)
#include <cuda_runtime.h>
#include <math.h>

#define EDG 24000
#define NN  8000
#define IV3 0.5773502691896257645f  // 1/sqrt(3)

// ---------------- static device scratch ----------------
__device__ float g_h   [EDG * 128];
__device__ float g_nm  [NN * 112];
__device__ float g_FA  [NN * 2048];
__device__ float g_gsgg[NN * 48];
__device__ float g_FB  [NN * 3 * 2560];
__device__ float g_gvf [NN * 3 * 32];
__device__ float g_xg  [NN * 112];
__device__ float g_sums[NN * 112];
__device__ float g_cnt [NN];
__device__ float g_th  [NN * 112];
__device__ float g_WA  [2048 * 48];
__device__ float g_WB  [2560 * 32];

// ---------------- f32x2 helpers ----------------
__device__ __forceinline__ unsigned long long dup_f32x2(float v) {
    unsigned long long r;
    asm("mov.b64 %0, {%1, %1};" : "=l"(r) : "f"(v));
    return r;
}
__device__ __forceinline__ void fma_f32x2(unsigned long long& d,
                                          unsigned long long a, unsigned long long b) {
    asm("fma.rn.f32x2 %0, %1, %2, %0;" : "+l"(d) : "l"(a), "l"(b));
}
__device__ __forceinline__ void unpack_f32x2(unsigned long long v, float& lo, float& hi) {
    asm("mov.b64 {%0, %1}, %2;" : "=f"(lo), "=f"(hi) : "l"(v));
}

// ---------------- zero accumulators ----------------
__global__ void zero_kernel() {
    int i = blockIdx.x * blockDim.x + threadIdx.x;
    const int T0 = NN * 112, T1 = 2 * NN * 112, T2 = 2 * NN * 112 + NN;
    if (i < T0)      g_nm[i] = 0.f;
    else if (i < T1) g_sums[i - T0] = 0.f;
    else if (i < T2) g_cnt[i - T1] = 0.f;
}

// ---------------- pack gate weight matrices ----------------
__global__ void prep_w_kernel(const float* __restrict__ Wg000, const float* __restrict__ Wg110,
                              const float* __restrict__ Wg001, const float* __restrict__ Wg111,
                              const float* __restrict__ Wg012, const float* __restrict__ Wg102) {
    int idx = blockIdx.x * blockDim.x + threadIdx.x;
    if (idx < 2048 * 48) {
        int k = idx / 48, j = idx % 48;
        float v;
        if (k < 1024) {
            int u = k >> 6, vv = k & 63;
            v = (j < 16) ? Wg000[(u * 64 + vv) * 16 + j]
                         : Wg001[(u * 64 + vv) * 32 + (j - 16)];
        } else {
            int kk = k - 1024; int u = kk >> 5, vv = kk & 31;
            v = (j < 16) ? Wg110[(u * 32 + vv) * 16 + j]
                         : Wg111[(u * 32 + vv) * 32 + (j - 16)];
        }
        g_WA[idx] = v;
    }
    int idx2 = idx - 2048 * 48;
    if (idx2 >= 0 && idx2 < 2560 * 32) {
        int k = idx2 / 32, w = idx2 & 31;
        float v;
        if (k < 512) { int u = k >> 5, vv = k & 31; v = Wg012[(u * 32 + vv) * 32 + w]; }
        else { int kk = k - 512; int u = kk >> 6, vv = kk & 63; v = Wg102[(u * 64 + vv) * 32 + w]; }
        g_WB[idx2] = v;
    }
}

// ---------------- radial MLP ----------------
__global__ void radial_kernel(const float* __restrict__ ea, const float* __restrict__ W1, float scale) {
    int idx = blockIdx.x * blockDim.x + threadIdx.x;
    if (idx >= EDG * 128) return;
    int e = idx >> 7, k = idx & 127;
    const float* a = ea + e * 4;
    float v = 0.5f * (a[0] * W1[k] + a[1] * W1[128 + k] + a[2] * W1[256 + k] + a[3] * W1[384 + k]);
    float s = v / (1.0f + expf(-v));
    g_h[idx] = scale * s;
}

// ---------------- FUSED edge kernel: GEMM (h @ W2) + contraction + scatter ----------------
// Block = 32 edges. Loops over 36 column chunks of 128 (K=128, double-buffered B).
// Contraction fused into per-chunk epilogue; no g_w materialization.
// smem layout (floats):
//  Ah   [128][36]      4608
//  Bs   [2][16][132]   4224
//  sxs0 [32][64]       2048
//  sxs1 [32][96]       3072
//  sa   [32][4]        128
//  sb   [32][32]       1024
//  smsg [32][160]      5120
//  sdst [32] ints
#define SM_AH   0
#define SM_BS   4608
#define SM_XS0  (4608 + 4224)
#define SM_XS1  (SM_XS0 + 2048)
#define SM_A    (SM_XS1 + 3072)
#define SM_B2   (SM_A + 128)
#define SM_MSG  (SM_B2 + 1024)
#define SM_TOTF (SM_MSG + 5120)
#define EDGE_SMEM_BYTES (SM_TOTF * 4 + 32 * 4)

__global__ void __launch_bounds__(256, 2) edge_fused(
        const float* __restrict__ h, const float* __restrict__ W2,
        const float* __restrict__ x, const float* __restrict__ ea,
        const int* __restrict__ eidx, float pw0, float pw1) {
    extern __shared__ float sm[];
    float* Ah   = sm + SM_AH;
    float* Bs   = sm + SM_BS;
    float* sxs0 = sm + SM_XS0;
    float* sxs1 = sm + SM_XS1;
    float* sa   = sm + SM_A;
    float* sb   = sm + SM_B2;
    float* smsg = sm + SM_MSG;
    int*   sdst = (int*)(sm + SM_TOTF);

    const int tid = threadIdx.x;
    const int bm = blockIdx.x * 32;

    // load A (h) transposed: Ah[k][e]
#pragma unroll
    for (int r = 0; r < 4; r++) {
        int f = tid + 256 * r;            // 0..1023
        int e = f >> 5, k4 = (f & 31) << 2;
        float4 v = *(const float4*)(h + (size_t)(bm + e) * 128 + k4);
        Ah[(k4 + 0) * 36 + e] = v.x;
        Ah[(k4 + 1) * 36 + e] = v.y;
        Ah[(k4 + 2) * 36 + e] = v.z;
        Ah[(k4 + 3) * 36 + e] = v.w;
    }
    // per-edge coefficients
    {
        int e = tid >> 3, part = tid & 7;
        int src = eidx[bm + e];
        for (int i = part; i < 160; i += 8) {
            float v = x[src * 160 + i];
            if (i < 64) sxs0[e * 64 + i] = v;
            else        sxs1[e * 96 + (i - 64)] = v;
        }
        if (part == 0) sdst[e] = eidx[EDG + bm + e];
        if (part < 4)  sa[e * 4 + part] = ea[(bm + e) * 4 + part];
    }
    for (int i = tid; i < 32 * 160; i += 256) smsg[i] = 0.f;
    __syncthreads();
    // b[e][u] = xs1[e][u] . a1[e]
    for (int i = tid; i < 32 * 32; i += 256) {
        int e = i >> 5, u = i & 31;
        sb[i] = sxs1[e * 96 + u * 3 + 0] * sa[e * 4 + 1]
              + sxs1[e * 96 + u * 3 + 1] * sa[e * 4 + 2]
              + sxs1[e * 96 + u * 3 + 2] * sa[e * 4 + 3];
    }
    __syncthreads();

    const int tg = tid >> 4;     // 0..15
    const int tl = tid & 15;     // 0..15
    const int e0 = tg * 2;       // 2 edges per thread
    const int tn = tl * 8;       // 8 cols per thread

    for (int nc = 0; nc < 36; nc++) {
        unsigned long long acc[2][4];
#pragma unroll
        for (int i = 0; i < 2; i++)
#pragma unroll
            for (int j = 0; j < 4; j++) acc[i][j] = 0ULL;

        // prologue: load k-chunk 0 into buf 0
        {
            int f0 = tid,       kk0 = f0 >> 5, c40 = (f0 & 31) << 2;
            int f1 = tid + 256, kk1 = f1 >> 5, c41 = (f1 & 31) << 2;
            *(float4*)(Bs + kk0 * 132 + c40) =
                *(const float4*)(W2 + (size_t)kk0 * 4608 + nc * 128 + c40);
            *(float4*)(Bs + kk1 * 132 + c41) =
                *(const float4*)(W2 + (size_t)kk1 * 4608 + nc * 128 + c41);
        }
        __syncthreads();

        for (int kc = 0; kc < 8; kc++) {
            float4 pA, pB;
            int kk0 = tid >> 5, c40 = (tid & 31) << 2;
            int kk1 = (tid + 256) >> 5, c41 = c40;
            if (kc < 7) {
                pA = *(const float4*)(W2 + (size_t)((kc + 1) * 16 + kk0) * 4608 + nc * 128 + c40);
                pB = *(const float4*)(W2 + (size_t)((kc + 1) * 16 + kk1) * 4608 + nc * 128 + c41);
            }
            const float* Bp = Bs + (kc & 1) * 2112;
#pragma unroll
            for (int kk = 0; kk < 16; kk++) {
                float a0 = Ah[(kc * 16 + kk) * 36 + e0];
                float a1 = Ah[(kc * 16 + kk) * 36 + e0 + 1];
                ulonglong2 q0 = *(const ulonglong2*)(Bp + kk * 132 + tn);
                ulonglong2 q1 = *(const ulonglong2*)(Bp + kk * 132 + tn + 4);
                unsigned long long d0 = dup_f32x2(a0), d1 = dup_f32x2(a1);
                fma_f32x2(acc[0][0], d0, q0.x); fma_f32x2(acc[0][1], d0, q0.y);
                fma_f32x2(acc[0][2], d0, q1.x); fma_f32x2(acc[0][3], d0, q1.y);
                fma_f32x2(acc[1][0], d1, q0.x); fma_f32x2(acc[1][1], d1, q0.y);
                fma_f32x2(acc[1][2], d1, q1.x); fma_f32x2(acc[1][3], d1, q1.y);
            }
            if (kc < 7) {
                float* Bw = Bs + ((kc + 1) & 1) * 2112;
                *(float4*)(Bw + kk0 * 132 + c40) = pA;
                *(float4*)(Bw + kk1 * 132 + c41) = pB;
            }
            __syncthreads();
        }

        // ---- epilogue: contraction over u via shuffle reduction ----
        float accf[2][8];
#pragma unroll
        for (int i = 0; i < 2; i++)
#pragma unroll
            for (int j = 0; j < 4; j++)
                unpack_f32x2(acc[i][j], accf[i][2 * j], accf[i][2 * j + 1]);

        if (nc < 8) {            // section 000 -> t000 (w:16)
            int u_g = nc * 8 + (tl >> 1);
            int w0 = (tl & 1) * 8;
            float c0 = sxs0[e0 * 64 + u_g], c1 = sxs0[(e0 + 1) * 64 + u_g];
            float r[2][8];
#pragma unroll
            for (int j = 0; j < 8; j++) { r[0][j] = c0 * accf[0][j]; r[1][j] = c1 * accf[1][j]; }
#pragma unroll
            for (int d = 2; d <= 8; d <<= 1)
#pragma unroll
                for (int i = 0; i < 2; i++)
#pragma unroll
                    for (int j = 0; j < 8; j++)
                        r[i][j] += __shfl_xor_sync(0xffffffffu, r[i][j], d);
            if (tl < 2)
#pragma unroll
                for (int i = 0; i < 2; i++)
#pragma unroll
                    for (int j = 0; j < 8; j++)
                        smsg[(e0 + i) * 160 + w0 + j] += r[i][j];
        } else if (nc < 24) {    // section 011 -> t011 (w:32)
            int u_g = (nc - 8) * 4 + (tl >> 2);
            int w0 = (tl & 3) * 8;
            float c0 = sxs0[e0 * 64 + u_g], c1 = sxs0[(e0 + 1) * 64 + u_g];
            float r[2][8];
#pragma unroll
            for (int j = 0; j < 8; j++) { r[0][j] = c0 * accf[0][j]; r[1][j] = c1 * accf[1][j]; }
#pragma unroll
            for (int d = 4; d <= 8; d <<= 1)
#pragma unroll
                for (int i = 0; i < 2; i++)
#pragma unroll
                    for (int j = 0; j < 8; j++)
                        r[i][j] += __shfl_xor_sync(0xffffffffu, r[i][j], d);
            if (tl < 4)
#pragma unroll
                for (int i = 0; i < 2; i++)
#pragma unroll
                    for (int j = 0; j < 8; j++)
                        smsg[(e0 + i) * 160 + 16 + w0 + j] += r[i][j];
        } else if (nc < 32) {    // section 101 -> t101[m] (w:32, 3 m)
            int u_g = (nc - 24) * 4 + (tl >> 2);
            int w0 = (tl & 3) * 8;
#pragma unroll
            for (int m = 0; m < 3; m++) {
                float c0 = sxs1[e0 * 96 + u_g * 3 + m];
                float c1 = sxs1[(e0 + 1) * 96 + u_g * 3 + m];
                float r[2][8];
#pragma unroll
                for (int j = 0; j < 8; j++) { r[0][j] = c0 * accf[0][j]; r[1][j] = c1 * accf[1][j]; }
#pragma unroll
                for (int d = 4; d <= 8; d <<= 1)
#pragma unroll
                    for (int i = 0; i < 2; i++)
#pragma unroll
                        for (int j = 0; j < 8; j++)
                            r[i][j] += __shfl_xor_sync(0xffffffffu, r[i][j], d);
                if (tl < 4)
#pragma unroll
                    for (int i = 0; i < 2; i++)
#pragma unroll
                        for (int j = 0; j < 8; j++)
                            smsg[(e0 + i) * 160 + 48 + m * 32 + w0 + j] += r[i][j];
            }
        } else {                 // section 110 -> t110 (w:16), coef b[u]
            int u_g = (nc - 32) * 8 + (tl >> 1);
            int w0 = (tl & 1) * 8;
            float c0 = sb[e0 * 32 + u_g], c1 = sb[(e0 + 1) * 32 + u_g];
            float r[2][8];
#pragma unroll
            for (int j = 0; j < 8; j++) { r[0][j] = c0 * accf[0][j]; r[1][j] = c1 * accf[1][j]; }
#pragma unroll
            for (int d = 2; d <= 8; d <<= 1)
#pragma unroll
                for (int i = 0; i < 2; i++)
#pragma unroll
                    for (int j = 0; j < 8; j++)
                        r[i][j] += __shfl_xor_sync(0xffffffffu, r[i][j], d);
            if (tl < 2)
#pragma unroll
                for (int i = 0; i < 2; i++)
#pragma unroll
                    for (int j = 0; j < 8; j++)
                        smsg[(e0 + i) * 160 + 144 + w0 + j] += r[i][j];
        }
    }
    __syncthreads();

    // ---- final: combine with a-coefs and scatter to g_nm ----
    for (int i = tid; i < 32 * 112; i += 256) {
        int e = i / 112, t = i - e * 112;
        const float* M = smsg + e * 160;
        float a0 = sa[e * 4];
        float v;
        if (t < 16) {
            v = pw0 * (a0 * M[t] + IV3 * M[144 + t]);
        } else {
            int j = t - 16; int w = j / 3, m = j - w * 3;
            v = pw1 * IV3 * (sa[e * 4 + 1 + m] * M[16 + w] + a0 * M[48 + m * 32 + w]);
        }
        atomicAdd(&g_nm[sdst[e] * 112 + t], v);
    }
}

// ---------------- generic register-tiled fp32 GEMM ----------------
template<int BM, int BN, int BK, int TM, int TN>
__global__ void gemm_kernel(const float* __restrict__ A, const float* __restrict__ B,
                            float* __restrict__ C, int M, int N, int K) {
    __shared__ float As[BM][BK + 1];
    __shared__ float Bs[BK][BN + 4];
    const int nThreads = (BM / TM) * (BN / TN);
    const int tid = threadIdx.x;
    const int block_m = blockIdx.y * BM;
    const int block_n = blockIdx.x * BN;
    const int tm = (tid / (BN / TN)) * TM;
    const int tn = (tid % (BN / TN)) * TN;

    float acc[TM][TN];
#pragma unroll
    for (int i = 0; i < TM; i++)
#pragma unroll
        for (int j = 0; j < TN; j++) acc[i][j] = 0.f;

    for (int k0 = 0; k0 < K; k0 += BK) {
        for (int i = tid; i < BM * BK; i += nThreads) {
            int m = i / BK, kk = i % BK;
            int gm = block_m + m, gk = k0 + kk;
            float v = 0.f;
            if (gm < M && gk < K) v = A[(size_t)gm * K + gk];
            As[m][kk] = v;
        }
        for (int i = tid; i < BK * BN; i += nThreads) {
            int kk = i / BN, n = i % BN;
            int gk = k0 + kk, gn = block_n + n;
            float v = 0.f;
            if (gk < K && gn < N) v = B[(size_t)gk * N + gn];
            Bs[kk][n] = v;
        }
        __syncthreads();
#pragma unroll
        for (int kk = 0; kk < BK; kk++) {
            float av[TM], bv[TN];
#pragma unroll
            for (int i = 0; i < TM; i++) av[i] = As[tm + i][kk];
#pragma unroll
            for (int j = 0; j < TN; j++) bv[j] = Bs[kk][tn + j];
#pragma unroll
            for (int i = 0; i < TM; i++)
#pragma unroll
                for (int j = 0; j < TN; j++) acc[i][j] = fmaf(av[i], bv[j], acc[i][j]);
        }
        __syncthreads();
    }
#pragma unroll
    for (int i = 0; i < TM; i++) {
        int gm = block_m + tm + i;
        if (gm >= M) continue;
#pragma unroll
        for (int j = 0; j < TN; j++) {
            int gn = block_n + tn + j;
            if (gn < N) C[(size_t)gm * N + gn] = acc[i][j];
        }
    }
}

// ---------------- gate feature builders ----------------
__global__ void build_fa_kernel(const float* __restrict__ x, float pwg01) {
    int idx = blockIdx.x * blockDim.x + threadIdx.x;
    if (idx >= NN * 2048) return;
    int n = idx >> 11, k = idx & 2047;
    float v;
    if (k < 1024) {
        int u = k >> 6, vv = k & 63;
        v = pwg01 * g_nm[n * 112 + u] * x[n * 160 + vv];
    } else {
        int kk = k - 1024; int u = kk >> 5, vv = kk & 31;
        const float* m1 = g_nm + n * 112 + 16 + u * 3;
        const float* x1 = x + n * 160 + 64 + vv * 3;
        v = pwg01 * IV3 * (m1[0] * x1[0] + m1[1] * x1[1] + m1[2] * x1[2]);
    }
    g_FA[idx] = v;
}

__global__ void build_fb_kernel(const float* __restrict__ x, float c) {
    int idx = blockIdx.x * blockDim.x + threadIdx.x;
    if (idx >= NN * 3 * 2560) return;
    int row = idx / 2560, k = idx - row * 2560;
    int n = row / 3, m = row - n * 3;
    float v;
    if (k < 512) {
        int u = k >> 5, vv = k & 31;
        v = c * g_nm[n * 112 + u] * x[n * 160 + 64 + vv * 3 + m];
    } else {
        int kk = k - 512; int u = kk >> 6, vv = kk & 63;
        v = c * g_nm[n * 112 + 16 + u * 3 + m] * x[n * 160 + vv];
    }
    g_FB[idx] = v;
}

// ---------------- gates + masked segment scatter ----------------
__global__ void xg_kernel(const int* __restrict__ z, const int* __restrict__ can,
                          float cst_sig, float cst_tanh) {
    int idx = blockIdx.x * blockDim.x + threadIdx.x;
    if (idx >= NN * 112) return;
    int n = idx / 112, t = idx - n * 112;
    float v;
    if (t < 16) {
        v = cst_sig / (1.0f + expf(-g_gsgg[n * 48 + t]));
    } else {
        int j = t - 16; int w = j / 3, m = j - w * 3;
        float gate = cst_tanh * tanhf(g_gsgg[n * 48 + 16 + w]);
        v = gate * g_gvf[(n * 3 + m) * 32 + w];
    }
    g_xg[idx] = v;
    if (z[n] > 1) {
        atomicAdd(&g_sums[can[n] * 112 + t], v);
        if (t == 0) atomicAdd(&g_cnt[can[n]], 1.0f);
    }
}

// ---------------- th (second-order node update) ----------------
__global__ void th_kernel(const float* __restrict__ Wa, const float* __restrict__ Wb,
                          const float* __restrict__ Wc, const float* __restrict__ Wd,
                          float pwh0, float pwh1) {
    int n = blockIdx.x, tid = threadIdx.x;  // 128 threads
    __shared__ float sh[112];
    __shared__ float sD[1024];
    __shared__ float sc1[32];
    __shared__ float spart[128];
    float inv = 1.0f / fmaxf(g_cnt[n], 1.0f);
    if (tid < 112) sh[tid] = g_sums[n * 112 + tid] * inv;
    __syncthreads();
    for (int k = tid; k < 1024; k += 128) {
        int u = k >> 5, v = k & 31;
        const float* hu = sh + 16 + u * 3;
        const float* hv = sh + 16 + v * 3;
        sD[k] = hu[0] * hv[0] + hu[1] * hv[1] + hu[2] * hv[2];
    }
    if (tid < 32) {
        float acc = 0.f;
#pragma unroll
        for (int k = 0; k < 16; k++) acc += (Wb[k * 32 + tid] + Wc[tid * 16 + k]) * sh[k];
        sc1[tid] = acc;
    }
    __syncthreads();
    {
        int w = tid & 15, p = tid >> 4;
        float acc = 0.f;
        for (int k = p * 128; k < p * 128 + 128; k++) acc = fmaf(sD[k], Wd[k * 16 + w], acc);
        spart[tid] = acc;
    }
    __syncthreads();
    if (tid < 112) {
        float v;
        if (tid < 16) {
            float t0b = 0.f;
#pragma unroll
            for (int p = 0; p < 8; p++) t0b += spart[p * 16 + tid];
            float wa = 0.f;
#pragma unroll
            for (int q = 0; q < 16; q++) wa = fmaf(Wa[tid * 16 + q], sh[q], wa);
            v = pwh0 * (sh[tid] * wa + IV3 * t0b);
        } else {
            int u = (tid - 16) / 3;
            v = pwh1 * IV3 * sh[tid] * sc1[u];
        }
        g_th[n * 112 + tid] = v;
    }
}

// ---------------- final select + linear ----------------
__global__ void out_kernel(const float* __restrict__ WL0, const float* __restrict__ WL1,
                           const int* __restrict__ z, const int* __restrict__ can,
                           float* __restrict__ out) {
    int n = blockIdx.x, tid = threadIdx.x;  // 128 threads
    __shared__ float sy[112];
    bool mask = z[n] > 1;
    int c = can[n];
    const float* y = mask ? (g_th + (size_t)c * 112) : (g_xg + (size_t)n * 112);
    if (tid < 112) sy[tid] = y[tid];
    __syncthreads();
    if (tid < 112) {
        float v = 0.f;
        if (tid < 16) {
#pragma unroll
            for (int u = 0; u < 16; u++) v = fmaf(sy[u], WL0[u * 16 + tid], v);
            v *= 0.25f;
        } else {
            int j = tid - 16; int w = j / 3, m = j - w * 3;
#pragma unroll
            for (int u = 0; u < 32; u++) v = fmaf(sy[16 + u * 3 + m], WL1[u * 32 + w], v);
            v *= 0.17677669529663687f;  // 1/sqrt(32)
        }
        out[(size_t)n * 112 + tid] = v;
    }
}

// ---------------- host: normalization constants (exact np.trapz match) ----------------
static void host_csts(double& c_silu, double& c_sig, double& c_tanh) {
    const int NPT = 200001;
    const double lo = -12.0, hi = 12.0;
    const double step = (hi - lo) / (double)(NPT - 1);
    double s1 = 0.0, s2 = 0.0, s3 = 0.0;
    double p1 = 0.0, p2 = 0.0, p3 = 0.0;
    for (int i = 0; i < NPT; i++) {
        double xv = lo + step * i;
        double pdf = exp(-0.5 * xv * xv) * 0.3989422804014327;
        double sig = 1.0 / (1.0 + exp(-xv));
        double f1 = xv * sig; f1 = f1 * f1 * pdf;
        double f2 = sig * sig * pdf;
        double th = tanh(xv); double f3 = th * th * pdf;
        if (i > 0) { s1 += p1 + f1; s2 += p2 + f2; s3 += p3 + f3; }
        p1 = f1; p2 = f2; p3 = f3;
    }
    s1 *= 0.5 * step; s2 *= 0.5 * step; s3 *= 0.5 * step;
    c_silu = 1.0 / sqrt(s1);
    c_sig  = 1.0 / sqrt(s2);
    c_tanh = 1.0 / sqrt(s3);
}

extern "C" void kernel_launch(void* const* d_in, const int* in_sizes, int n_in,
                              void* d_out, int out_size) {
    const float* x     = (const float*)d_in[0];
    const float* ea    = (const float*)d_in[1];
    const float* W1    = (const float*)d_in[2];
    const float* W2    = (const float*)d_in[3];
    const float* Wg000 = (const float*)d_in[4];
    const float* Wg110 = (const float*)d_in[5];
    const float* Wg001 = (const float*)d_in[6];
    const float* Wg111 = (const float*)d_in[7];
    const float* Wg012 = (const float*)d_in[8];
    const float* Wg102 = (const float*)d_in[9];
    const float* Wa    = (const float*)d_in[10];
    const float* Wb    = (const float*)d_in[11];
    const float* Wc    = (const float*)d_in[12];
    const float* Wd    = (const float*)d_in[13];
    const float* WL0   = (const float*)d_in[14];
    const float* WL1   = (const float*)d_in[15];
    const int*   eidx  = (const int*)d_in[16];
    const int*   z     = (const int*)d_in[17];
    const int*   can   = (const int*)d_in[18];
    float* out = (float*)d_out;

    double c_silu_d, c_sig_d, c_tanh_d;
    host_csts(c_silu_d, c_sig_d, c_tanh_d);
    float radial_scale = (float)(c_silu_d / sqrt(128.0));
    float cst_sig  = (float)c_sig_d;
    float cst_tanh = (float)c_tanh_d;
    float pw_msg0 = (float)sqrt(1.0 / 96.0);
    float pw_msg1 = (float)sqrt(3.0 / 96.0);
    float pwg01   = (float)sqrt(1.0 / 2048.0);
    float pwg2c   = (float)(sqrt(3.0 / 2560.0) * (1.0 / sqrt(3.0)));
    float pwh0    = (float)sqrt(1.0 / 1040.0);
    float pwh1    = (float)sqrt(3.0 / 32.0);

    void *p_h, *p_FA, *p_gsgg, *p_FB, *p_gvf, *p_WA, *p_WB;
    cudaGetSymbolAddress(&p_h, g_h);
    cudaGetSymbolAddress(&p_FA, g_FA);
    cudaGetSymbolAddress(&p_gsgg, g_gsgg);
    cudaGetSymbolAddress(&p_FB, g_FB);
    cudaGetSymbolAddress(&p_gvf, g_gvf);
    cudaGetSymbolAddress(&p_WA, g_WA);
    cudaGetSymbolAddress(&p_WB, g_WB);

    cudaFuncSetAttribute(edge_fused, cudaFuncAttributeMaxDynamicSharedMemorySize, EDGE_SMEM_BYTES);

    // 1. zero accumulators
    zero_kernel<<<(2 * NN * 112 + NN + 255) / 256, 256>>>();
    // 2. pack gate weights
    prep_w_kernel<<<(2048 * 48 + 2560 * 32 + 255) / 256, 256>>>(Wg000, Wg110, Wg001, Wg111, Wg012, Wg102);
    // 3. radial features
    radial_kernel<<<(EDG * 128 + 255) / 256, 256>>>(ea, W1, radial_scale);
    // 4. FUSED: GEMM + message contraction + scatter (no g_w round trip)
    edge_fused<<<EDG / 32, 256, EDGE_SMEM_BYTES>>>(
        (const float*)p_h, W2, x, ea, eidx, pw_msg0, pw_msg1);
    // 5. gate features A; GEMM -> gs|gg
    build_fa_kernel<<<(NN * 2048 + 255) / 256, 256>>>(x, pwg01);
    gemm_kernel<64, 48, 16, 4, 4><<<dim3(1, NN / 64), 192>>>(
        (const float*)p_FA, (const float*)p_WA, (float*)p_gsgg, NN, 48, 2048);
    // 6. gate features B; GEMM -> gv
    build_fb_kernel<<<(NN * 3 * 2560 + 255) / 256, 256>>>(x, pwg2c);
    gemm_kernel<64, 32, 16, 4, 4><<<dim3(1, NN * 3 / 64), 128>>>(
        (const float*)p_FB, (const float*)p_WB, (float*)p_gvf, NN * 3, 32, 2560);
    // 7. gates + masked segment-sum scatter
    xg_kernel<<<(NN * 112 + 255) / 256, 256>>>(z, can, cst_sig, cst_tanh);
    // 8. second-order node update
    th_kernel<<<NN, 128>>>(Wa, Wb, Wc, Wd, pwh0, pwh1);
    // 9. final select + linear
    out_kernel<<<NN, 128>>>(WL0, WL1, z, can, out);
}

// round 15
// speedup vs baseline: 1.4808x; 1.4808x over previous
#include <cuda_runtime.h>
#include <math.h>

#define EDG 24000
#define NN  8000
#define IV3 0.5773502691896257645f  // 1/sqrt(3)

// ---------------- static device scratch ----------------
__device__ float g_h   [EDG * 128];
__device__ float g_w   [EDG * 4608];       // per-edge weights (442 MB)
__device__ float g_nm  [NN * 112];
__device__ float g_FA  [NN * 2048];
__device__ float g_gsgg[NN * 48];
__device__ float g_FB  [NN * 3 * 2560];    // 246 MB
__device__ float g_gvf [NN * 3 * 32];
__device__ float g_xg  [NN * 112];
__device__ float g_sums[NN * 112];
__device__ float g_cnt [NN];
__device__ float g_th  [NN * 112];
__device__ float g_WA  [2048 * 48];
__device__ float g_WB  [2560 * 32];

// ---------------- f32x2 helpers ----------------
__device__ __forceinline__ unsigned long long dup_f32x2(float v) {
    unsigned long long r;
    asm("mov.b64 %0, {%1, %1};" : "=l"(r) : "f"(v));
    return r;
}
__device__ __forceinline__ void fma_f32x2(unsigned long long& d,
                                          unsigned long long a, unsigned long long b) {
    asm("fma.rn.f32x2 %0, %1, %2, %0;" : "+l"(d) : "l"(a), "l"(b));
}
__device__ __forceinline__ void unpack_f32x2(unsigned long long v, float& lo, float& hi) {
    asm("mov.b64 {%0, %1}, %2;" : "=f"(lo), "=f"(hi) : "l"(v));
}

// ---------------- zero accumulators ----------------
__global__ void zero_kernel() {
    int i = blockIdx.x * blockDim.x + threadIdx.x;
    const int T0 = NN * 112, T1 = 2 * NN * 112, T2 = 2 * NN * 112 + NN;
    if (i < T0)      g_nm[i] = 0.f;
    else if (i < T1) g_sums[i - T0] = 0.f;
    else if (i < T2) g_cnt[i - T1] = 0.f;
}

// ---------------- pack gate weight matrices ----------------
__global__ void prep_w_kernel(const float* __restrict__ Wg000, const float* __restrict__ Wg110,
                              const float* __restrict__ Wg001, const float* __restrict__ Wg111,
                              const float* __restrict__ Wg012, const float* __restrict__ Wg102) {
    int idx = blockIdx.x * blockDim.x + threadIdx.x;
    if (idx < 2048 * 48) {
        int k = idx / 48, j = idx % 48;
        float v;
        if (k < 1024) {
            int u = k >> 6, vv = k & 63;
            v = (j < 16) ? Wg000[(u * 64 + vv) * 16 + j]
                         : Wg001[(u * 64 + vv) * 32 + (j - 16)];
        } else {
            int kk = k - 1024; int u = kk >> 5, vv = kk & 31;
            v = (j < 16) ? Wg110[(u * 32 + vv) * 16 + j]
                         : Wg111[(u * 32 + vv) * 32 + (j - 16)];
        }
        g_WA[idx] = v;
    }
    int idx2 = idx - 2048 * 48;
    if (idx2 >= 0 && idx2 < 2560 * 32) {
        int k = idx2 / 32, w = idx2 & 31;
        float v;
        if (k < 512) { int u = k >> 5, vv = k & 31; v = Wg012[(u * 32 + vv) * 32 + w]; }
        else { int kk = k - 512; int u = kk >> 6, vv = kk & 63; v = Wg102[(u * 64 + vv) * 32 + w]; }
        g_WB[idx2] = v;
    }
}

// ---------------- radial MLP ----------------
__global__ void radial_kernel(const float* __restrict__ ea, const float* __restrict__ W1, float scale) {
    int idx = blockIdx.x * blockDim.x + threadIdx.x;
    if (idx >= EDG * 128) return;
    int e = idx >> 7, k = idx & 127;
    const float* a = ea + e * 4;
    float v = 0.5f * (a[0] * W1[k] + a[1] * W1[128 + k] + a[2] * W1[256 + k] + a[3] * W1[384 + k]);
    float s = v / (1.0f + expf(-v));
    g_h[idx] = scale * s;
}

// ---------------- big GEMM: f32x2 FMA + double-buffered smem with register prefetch ----------------
// C[M,4608] = A[M,128] @ B[128,4608]. 128x128 tile, BK=16, 256 threads, 8x8/thread.
#define GK 128
#define GN 4608
__global__ void __launch_bounds__(256) gemm_big(const float* __restrict__ A,
                                                const float* __restrict__ B,
                                                float* __restrict__ C, int M) {
    __shared__ float As[2][16][132];   // transposed A tile: As[buf][kk][m]
    __shared__ float Bs[2][16][132];   // Bs[buf][kk][n]
    const int tid = threadIdx.x;
    const int bm = blockIdx.y * 128;
    const int bn = blockIdx.x * 128;
    const int tm = (tid >> 4) << 3;
    const int tn = (tid & 15) << 3;

    // load indices (each thread: 2 float4 for A, 2 float4 for B per tile)
    const int a_row0 = tid >> 2,          a_col0 = (tid & 3) << 2;         // f = tid
    const int a_row1 = (tid + 256) >> 2,  a_col1 = a_col0;                 // f = tid+256
    const int b_row0 = tid >> 5,          b_col0 = (tid & 31) << 2;
    const int b_row1 = (tid + 256) >> 5,  b_col1 = b_col0;

    unsigned long long acc[8][4];
#pragma unroll
    for (int i = 0; i < 8; i++)
#pragma unroll
        for (int j = 0; j < 4; j++) acc[i][j] = 0ULL;

    // prologue: tile 0 -> buf 0
    {
        float4 va0 = make_float4(0.f, 0.f, 0.f, 0.f), va1 = va0;
        if (bm + a_row0 < M) va0 = *(const float4*)(A + (size_t)(bm + a_row0) * GK + a_col0);
        if (bm + a_row1 < M) va1 = *(const float4*)(A + (size_t)(bm + a_row1) * GK + a_col1);
        As[0][a_col0 + 0][a_row0] = va0.x; As[0][a_col0 + 1][a_row0] = va0.y;
        As[0][a_col0 + 2][a_row0] = va0.z; As[0][a_col0 + 3][a_row0] = va0.w;
        As[0][a_col1 + 0][a_row1] = va1.x; As[0][a_col1 + 1][a_row1] = va1.y;
        As[0][a_col1 + 2][a_row1] = va1.z; As[0][a_col1 + 3][a_row1] = va1.w;
        *(float4*)&Bs[0][b_row0][b_col0] = *(const float4*)(B + (size_t)b_row0 * GN + bn + b_col0);
        *(float4*)&Bs[0][b_row1][b_col1] = *(const float4*)(B + (size_t)b_row1 * GN + bn + b_col1);
    }
    __syncthreads();

#pragma unroll
    for (int t = 0; t < 8; t++) {
        const int cur = t & 1, nxt = cur ^ 1;
        float4 pa0, pa1, pb0, pb1;
        if (t < 7) {
            const int k0 = (t + 1) * 16;
            pa0 = make_float4(0.f, 0.f, 0.f, 0.f); pa1 = pa0;
            if (bm + a_row0 < M) pa0 = *(const float4*)(A + (size_t)(bm + a_row0) * GK + k0 + a_col0);
            if (bm + a_row1 < M) pa1 = *(const float4*)(A + (size_t)(bm + a_row1) * GK + k0 + a_col1);
            pb0 = *(const float4*)(B + (size_t)(k0 + b_row0) * GN + bn + b_col0);
            pb1 = *(const float4*)(B + (size_t)(k0 + b_row1) * GN + bn + b_col1);
        }
#pragma unroll
        for (int kk = 0; kk < 16; kk++) {
            float av[8];
            *(float4*)&av[0] = *(const float4*)&As[cur][kk][tm];
            *(float4*)&av[4] = *(const float4*)&As[cur][kk][tm + 4];
            ulonglong2 q0 = *(const ulonglong2*)&Bs[cur][kk][tn];
            ulonglong2 q1 = *(const ulonglong2*)&Bs[cur][kk][tn + 4];
#pragma unroll
            for (int i = 0; i < 8; i++) {
                unsigned long long a2 = dup_f32x2(av[i]);
                fma_f32x2(acc[i][0], a2, q0.x);
                fma_f32x2(acc[i][1], a2, q0.y);
                fma_f32x2(acc[i][2], a2, q1.x);
                fma_f32x2(acc[i][3], a2, q1.y);
            }
        }
        if (t < 7) {
            As[nxt][a_col0 + 0][a_row0] = pa0.x; As[nxt][a_col0 + 1][a_row0] = pa0.y;
            As[nxt][a_col0 + 2][a_row0] = pa0.z; As[nxt][a_col0 + 3][a_row0] = pa0.w;
            As[nxt][a_col1 + 0][a_row1] = pa1.x; As[nxt][a_col1 + 1][a_row1] = pa1.y;
            As[nxt][a_col1 + 2][a_row1] = pa1.z; As[nxt][a_col1 + 3][a_row1] = pa1.w;
            *(float4*)&Bs[nxt][b_row0][b_col0] = pb0;
            *(float4*)&Bs[nxt][b_row1][b_col1] = pb1;
            __syncthreads();
        }
    }

#pragma unroll
    for (int i = 0; i < 8; i++) {
        int gm = bm + tm + i;
        if (gm >= M) continue;
        float o[8];
#pragma unroll
        for (int j = 0; j < 4; j++) unpack_f32x2(acc[i][j], o[2 * j], o[2 * j + 1]);
        float* cp = C + (size_t)gm * GN + bn + tn;
        *(float4*)cp       = make_float4(o[0], o[1], o[2], o[3]);
        *(float4*)(cp + 4) = make_float4(o[4], o[5], o[6], o[7]);
    }
}

// ---------------- generic register-tiled fp32 GEMM ----------------
template<int BM, int BN, int BK, int TM, int TN>
__global__ void gemm_kernel(const float* __restrict__ A, const float* __restrict__ B,
                            float* __restrict__ C, int M, int N, int K) {
    __shared__ float As[BM][BK + 1];
    __shared__ float Bs[BK][BN + 4];
    const int nThreads = (BM / TM) * (BN / TN);
    const int tid = threadIdx.x;
    const int block_m = blockIdx.y * BM;
    const int block_n = blockIdx.x * BN;
    const int tm = (tid / (BN / TN)) * TM;
    const int tn = (tid % (BN / TN)) * TN;

    float acc[TM][TN];
#pragma unroll
    for (int i = 0; i < TM; i++)
#pragma unroll
        for (int j = 0; j < TN; j++) acc[i][j] = 0.f;

    for (int k0 = 0; k0 < K; k0 += BK) {
        for (int i = tid; i < BM * BK; i += nThreads) {
            int m = i / BK, kk = i % BK;
            int gm = block_m + m, gk = k0 + kk;
            float v = 0.f;
            if (gm < M && gk < K) v = A[(size_t)gm * K + gk];
            As[m][kk] = v;
        }
        for (int i = tid; i < BK * BN; i += nThreads) {
            int kk = i / BN, n = i % BN;
            int gk = k0 + kk, gn = block_n + n;
            float v = 0.f;
            if (gk < K && gn < N) v = B[(size_t)gk * N + gn];
            Bs[kk][n] = v;
        }
        __syncthreads();
#pragma unroll
        for (int kk = 0; kk < BK; kk++) {
            float av[TM], bv[TN];
#pragma unroll
            for (int i = 0; i < TM; i++) av[i] = As[tm + i][kk];
#pragma unroll
            for (int j = 0; j < TN; j++) bv[j] = Bs[kk][tn + j];
#pragma unroll
            for (int i = 0; i < TM; i++)
#pragma unroll
                for (int j = 0; j < TN; j++) acc[i][j] = fmaf(av[i], bv[j], acc[i][j]);
        }
        __syncthreads();
    }
#pragma unroll
    for (int i = 0; i < TM; i++) {
        int gm = block_m + tm + i;
        if (gm >= M) continue;
#pragma unroll
        for (int j = 0; j < TN; j++) {
            int gn = block_n + tn + j;
            if (gn < N) C[(size_t)gm * N + gn] = acc[i][j];
        }
    }
}

// ---------------- per-edge message contraction + scatter (R11 version) ----------------
__global__ void msg_kernel(const float* __restrict__ x, const float* __restrict__ ea,
                           const int* __restrict__ eidx, float pw_msg0, float pw_msg1) {
    int e = blockIdx.x;
    int tid = threadIdx.x;  // 128 threads
    __shared__ float sx0[64], sx1[96], sa[4], sb[32];
    __shared__ float sres[160];

    int src = eidx[e], dst = eidx[EDG + e];
    for (int i = tid; i < 160; i += 128) {
        float v = x[src * 160 + i];
        if (i < 64) sx0[i] = v; else sx1[i - 64] = v;
    }
    if (tid < 4) sa[tid] = ea[e * 4 + tid];
    __syncthreads();
    if (tid < 32)
        sb[tid] = sx1[tid * 3] * sa[1] + sx1[tid * 3 + 1] * sa[2] + sx1[tid * 3 + 2] * sa[3];
    __syncthreads();

    const float* wr = g_w + (size_t)e * 4608;
    if (tid < 16) {                       // s000
        int w = tid; float acc = 0.f;
#pragma unroll 4
        for (int u = 0; u < 64; u++) acc = fmaf(sx0[u], wr[u * 16 + w], acc);
        sres[w] = acc;
    } else if (tid < 32) {                // s110 (b = xs1 . a1)
        int w = tid - 16; float acc = 0.f;
#pragma unroll 4
        for (int u = 0; u < 32; u++) acc = fmaf(sb[u], wr[4096 + u * 16 + w], acc);
        sres[16 + w] = acc;
    } else if (tid < 64) {                // s011
        int w = tid - 32; float acc = 0.f;
#pragma unroll 4
        for (int u = 0; u < 64; u++) acc = fmaf(sx0[u], wr[1024 + u * 32 + w], acc);
        sres[32 + w] = acc;
    } else if (tid < 96) {                // s101, 3 m-components
        int w = tid - 64; float a0 = 0.f, a1 = 0.f, a2 = 0.f;
#pragma unroll 4
        for (int u = 0; u < 32; u++) {
            float v = wr[3072 + u * 32 + w];
            a0 = fmaf(sx1[u * 3 + 0], v, a0);
            a1 = fmaf(sx1[u * 3 + 1], v, a1);
            a2 = fmaf(sx1[u * 3 + 2], v, a2);
        }
        sres[64 + w] = a0; sres[96 + w] = a1; sres[128 + w] = a2;
    }
    __syncthreads();

    if (tid < 112) {
        float v;
        if (tid < 16) {
            v = pw_msg0 * (sa[0] * sres[tid] + IV3 * sres[16 + tid]);
        } else {
            int j = tid - 16; int w = j / 3, m = j - w * 3;
            v = pw_msg1 * IV3 * (sa[1 + m] * sres[32 + w] + sa[0] * sres[64 + m * 32 + w]);
        }
        atomicAdd(&g_nm[dst * 112 + tid], v);
    }
}

// ---------------- gate feature builders ----------------
__global__ void build_fa_kernel(const float* __restrict__ x, float pwg01) {
    int idx = blockIdx.x * blockDim.x + threadIdx.x;
    if (idx >= NN * 2048) return;
    int n = idx >> 11, k = idx & 2047;
    float v;
    if (k < 1024) {
        int u = k >> 6, vv = k & 63;
        v = pwg01 * g_nm[n * 112 + u] * x[n * 160 + vv];
    } else {
        int kk = k - 1024; int u = kk >> 5, vv = kk & 31;
        const float* m1 = g_nm + n * 112 + 16 + u * 3;
        const float* x1 = x + n * 160 + 64 + vv * 3;
        v = pwg01 * IV3 * (m1[0] * x1[0] + m1[1] * x1[1] + m1[2] * x1[2]);
    }
    g_FA[idx] = v;
}

__global__ void build_fb_kernel(const float* __restrict__ x, float c) {
    int idx = blockIdx.x * blockDim.x + threadIdx.x;
    if (idx >= NN * 3 * 2560) return;
    int row = idx / 2560, k = idx - row * 2560;
    int n = row / 3, m = row - n * 3;
    float v;
    if (k < 512) {
        int u = k >> 5, vv = k & 31;
        v = c * g_nm[n * 112 + u] * x[n * 160 + 64 + vv * 3 + m];
    } else {
        int kk = k - 512; int u = kk >> 6, vv = kk & 63;
        v = c * g_nm[n * 112 + 16 + u * 3 + m] * x[n * 160 + vv];
    }
    g_FB[idx] = v;
}

// ---------------- gates + masked segment scatter ----------------
__global__ void xg_kernel(const int* __restrict__ z, const int* __restrict__ can,
                          float cst_sig, float cst_tanh) {
    int idx = blockIdx.x * blockDim.x + threadIdx.x;
    if (idx >= NN * 112) return;
    int n = idx / 112, t = idx - n * 112;
    float v;
    if (t < 16) {
        v = cst_sig / (1.0f + expf(-g_gsgg[n * 48 + t]));
    } else {
        int j = t - 16; int w = j / 3, m = j - w * 3;
        float gate = cst_tanh * tanhf(g_gsgg[n * 48 + 16 + w]);
        v = gate * g_gvf[(n * 3 + m) * 32 + w];
    }
    g_xg[idx] = v;
    if (z[n] > 1) {
        atomicAdd(&g_sums[can[n] * 112 + t], v);
        if (t == 0) atomicAdd(&g_cnt[can[n]], 1.0f);
    }
}

// ---------------- th (second-order node update) ----------------
__global__ void th_kernel(const float* __restrict__ Wa, const float* __restrict__ Wb,
                          const float* __restrict__ Wc, const float* __restrict__ Wd,
                          float pwh0, float pwh1) {
    int n = blockIdx.x, tid = threadIdx.x;  // 128 threads
    __shared__ float sh[112];
    __shared__ float sD[1024];
    __shared__ float sc1[32];
    __shared__ float spart[128];
    float inv = 1.0f / fmaxf(g_cnt[n], 1.0f);
    if (tid < 112) sh[tid] = g_sums[n * 112 + tid] * inv;
    __syncthreads();
    for (int k = tid; k < 1024; k += 128) {
        int u = k >> 5, v = k & 31;
        const float* hu = sh + 16 + u * 3;
        const float* hv = sh + 16 + v * 3;
        sD[k] = hu[0] * hv[0] + hu[1] * hv[1] + hu[2] * hv[2];
    }
    if (tid < 32) {
        float acc = 0.f;
#pragma unroll
        for (int k = 0; k < 16; k++) acc += (Wb[k * 32 + tid] + Wc[tid * 16 + k]) * sh[k];
        sc1[tid] = acc;
    }
    __syncthreads();
    {
        int w = tid & 15, p = tid >> 4;
        float acc = 0.f;
        for (int k = p * 128; k < p * 128 + 128; k++) acc = fmaf(sD[k], Wd[k * 16 + w], acc);
        spart[tid] = acc;
    }
    __syncthreads();
    if (tid < 112) {
        float v;
        if (tid < 16) {
            float t0b = 0.f;
#pragma unroll
            for (int p = 0; p < 8; p++) t0b += spart[p * 16 + tid];
            float wa = 0.f;
#pragma unroll
            for (int q = 0; q < 16; q++) wa = fmaf(Wa[tid * 16 + q], sh[q], wa);
            v = pwh0 * (sh[tid] * wa + IV3 * t0b);
        } else {
            int u = (tid - 16) / 3;
            v = pwh1 * IV3 * sh[tid] * sc1[u];
        }
        g_th[n * 112 + tid] = v;
    }
}

// ---------------- final select + linear ----------------
__global__ void out_kernel(const float* __restrict__ WL0, const float* __restrict__ WL1,
                           const int* __restrict__ z, const int* __restrict__ can,
                           float* __restrict__ out) {
    int n = blockIdx.x, tid = threadIdx.x;  // 128 threads
    __shared__ float sy[112];
    bool mask = z[n] > 1;
    int c = can[n];
    const float* y = mask ? (g_th + (size_t)c * 112) : (g_xg + (size_t)n * 112);
    if (tid < 112) sy[tid] = y[tid];
    __syncthreads();
    if (tid < 112) {
        float v = 0.f;
        if (tid < 16) {
#pragma unroll
            for (int u = 0; u < 16; u++) v = fmaf(sy[u], WL0[u * 16 + tid], v);
            v *= 0.25f;
        } else {
            int j = tid - 16; int w = j / 3, m = j - w * 3;
#pragma unroll
            for (int u = 0; u < 32; u++) v = fmaf(sy[16 + u * 3 + m], WL1[u * 32 + w], v);
            v *= 0.17677669529663687f;  // 1/sqrt(32)
        }
        out[(size_t)n * 112 + tid] = v;
    }
}

// ---------------- host: normalization constants (exact np.trapz match) ----------------
static void host_csts(double& c_silu, double& c_sig, double& c_tanh) {
    const int NPT = 200001;
    const double lo = -12.0, hi = 12.0;
    const double step = (hi - lo) / (double)(NPT - 1);
    double s1 = 0.0, s2 = 0.0, s3 = 0.0;
    double p1 = 0.0, p2 = 0.0, p3 = 0.0;
    for (int i = 0; i < NPT; i++) {
        double xv = lo + step * i;
        double pdf = exp(-0.5 * xv * xv) * 0.3989422804014327;
        double sig = 1.0 / (1.0 + exp(-xv));
        double f1 = xv * sig; f1 = f1 * f1 * pdf;
        double f2 = sig * sig * pdf;
        double th = tanh(xv); double f3 = th * th * pdf;
        if (i > 0) { s1 += p1 + f1; s2 += p2 + f2; s3 += p3 + f3; }
        p1 = f1; p2 = f2; p3 = f3;
    }
    s1 *= 0.5 * step; s2 *= 0.5 * step; s3 *= 0.5 * step;
    c_silu = 1.0 / sqrt(s1);
    c_sig  = 1.0 / sqrt(s2);
    c_tanh = 1.0 / sqrt(s3);
}

extern "C" void kernel_launch(void* const* d_in, const int* in_sizes, int n_in,
                              void* d_out, int out_size) {
    const float* x     = (const float*)d_in[0];
    const float* ea    = (const float*)d_in[1];
    const float* W1    = (const float*)d_in[2];
    const float* W2    = (const float*)d_in[3];
    const float* Wg000 = (const float*)d_in[4];
    const float* Wg110 = (const float*)d_in[5];
    const float* Wg001 = (const float*)d_in[6];
    const float* Wg111 = (const float*)d_in[7];
    const float* Wg012 = (const float*)d_in[8];
    const float* Wg102 = (const float*)d_in[9];
    const float* Wa    = (const float*)d_in[10];
    const float* Wb    = (const float*)d_in[11];
    const float* Wc    = (const float*)d_in[12];
    const float* Wd    = (const float*)d_in[13];
    const float* WL0   = (const float*)d_in[14];
    const float* WL1   = (const float*)d_in[15];
    const int*   eidx  = (const int*)d_in[16];
    const int*   z     = (const int*)d_in[17];
    const int*   can   = (const int*)d_in[18];
    float* out = (float*)d_out;

    double c_silu_d, c_sig_d, c_tanh_d;
    host_csts(c_silu_d, c_sig_d, c_tanh_d);
    float radial_scale = (float)(c_silu_d / sqrt(128.0));
    float cst_sig  = (float)c_sig_d;
    float cst_tanh = (float)c_tanh_d;
    float pw_msg0 = (float)sqrt(1.0 / 96.0);
    float pw_msg1 = (float)sqrt(3.0 / 96.0);
    float pwg01   = (float)sqrt(1.0 / 2048.0);
    float pwg2c   = (float)(sqrt(3.0 / 2560.0) * (1.0 / sqrt(3.0)));
    float pwh0    = (float)sqrt(1.0 / 1040.0);
    float pwh1    = (float)sqrt(3.0 / 32.0);

    void *p_h, *p_w, *p_FA, *p_gsgg, *p_FB, *p_gvf, *p_WA, *p_WB;
    cudaGetSymbolAddress(&p_h, g_h);
    cudaGetSymbolAddress(&p_w, g_w);
    cudaGetSymbolAddress(&p_FA, g_FA);
    cudaGetSymbolAddress(&p_gsgg, g_gsgg);
    cudaGetSymbolAddress(&p_FB, g_FB);
    cudaGetSymbolAddress(&p_gvf, g_gvf);
    cudaGetSymbolAddress(&p_WA, g_WA);
    cudaGetSymbolAddress(&p_WB, g_WB);

    // 1. zero accumulators
    zero_kernel<<<(2 * NN * 112 + NN + 255) / 256, 256>>>();
    // 2. pack gate weights
    prep_w_kernel<<<(2048 * 48 + 2560 * 32 + 255) / 256, 256>>>(Wg000, Wg110, Wg001, Wg111, Wg012, Wg102);
    // 3. radial features
    radial_kernel<<<(EDG * 128 + 255) / 256, 256>>>(ea, W1, radial_scale);
    // 4. big GEMM (f32x2 + double-buffered): g_w = g_h @ W2
    gemm_big<<<dim3(4608 / 128, (EDG + 127) / 128), 256>>>(
        (const float*)p_h, W2, (float*)p_w, EDG);
    // 5. message contraction + scatter (R11 version)
    msg_kernel<<<EDG, 128>>>(x, ea, eidx, pw_msg0, pw_msg1);
    // 6. gate features A; GEMM -> gs|gg  (R11 grid)
    build_fa_kernel<<<(NN * 2048 + 255) / 256, 256>>>(x, pwg01);
    gemm_kernel<64, 48, 16, 4, 4><<<dim3(1, NN / 64), 192>>>(
        (const float*)p_FA, (const float*)p_WA, (float*)p_gsgg, NN, 48, 2048);
    // 7. gate features B; GEMM -> gv  (R11 grid)
    build_fb_kernel<<<(NN * 3 * 2560 + 255) / 256, 256>>>(x, pwg2c);
    gemm_kernel<64, 32, 16, 4, 4><<<dim3(1, NN * 3 / 64), 128>>>(
        (const float*)p_FB, (const float*)p_WB, (float*)p_gvf, NN * 3, 32, 2560);
    // 8. gates + masked segment-sum scatter
    xg_kernel<<<(NN * 112 + 255) / 256, 256>>>(z, can, cst_sig, cst_tanh);
    // 9. second-order node update
    th_kernel<<<NN, 128>>>(Wa, Wb, Wc, Wd, pwh0, pwh1);
    // 10. final select + linear
    out_kernel<<<NN, 128>>>(WL0, WL1, z, can, out);
}